// round 7
// baseline (speedup 1.0000x reference)
#include <cuda_runtime.h>
#include <cstdint>

#define HH 512
#define WW 512
#define BB 4
#define NCH 31          // IN_C + DEPTH
#define HW (HH * WW)

// Scratch: feats tensor [B][31][H][W]  (130 MB device global; written before read)
__device__ float g_feats[(size_t)BB * NCH * HW];

static __device__ __forceinline__ unsigned long long pk2(float x) {
    union { unsigned long long u; float f[2]; } t;
    t.f[0] = x; t.f[1] = x;
    return t.u;
}
#define FMA2(a, v, w) asm("fma.rn.f32x2 %0, %1, %2, %0;" \
                          : "+l"(a) : "l"(v), "l"(w))

// ---------------------------------------------------------------------------
// Init: feats[:,0] = x * sin_w + sin_b   (float4 vectorized)
// ---------------------------------------------------------------------------
__global__ void k_init(const float* __restrict__ x,
                       const float* __restrict__ sin_w,
                       const float* __restrict__ sin_b) {
    int idx = blockIdx.x * blockDim.x + threadIdx.x;   // 0 .. BB*HW/4-1
    float w = sin_w[0], b = sin_b[0];
    int bb = idx >> 16;            // HW/4 = 65536
    int p  = idx & 65535;
    float4 v = reinterpret_cast<const float4*>(x)[idx];
    float4 r = make_float4(fmaf(v.x, w, b), fmaf(v.y, w, b),
                           fmaf(v.z, w, b), fmaf(v.w, w, b));
    reinterpret_cast<float4*>(g_feats)[(size_t)(bb * NCH) * (HW / 4) + p] = r;
}

// ---------------------------------------------------------------------------
// ODD-D depth kernel: exact R2 champion. Tile 64x64, 256 threads,
// thread = 1 column x 16 rows. 88-wide double-buffered cp.async staging.
// ---------------------------------------------------------------------------
template<int D>
__global__ void __launch_bounds__(256)
k_depth(const float* __restrict__ Wmsd,
        const float* __restrict__ bias,
        int di) {
    constexpr int TILE = 64;
    constexpr int RPT  = 16;
    constexpr int TW   = 88;
    constexpr int TH   = TILE + 2 * D;
    constexpr int SBUF = TH * TW;
    constexpr int NV4  = TH * (TW / 4);

    extern __shared__ float sbuf[];

    const int nin = di + 1;
    const int tid = threadIdx.x;
    const int lx  = tid & 63;
    const int grp = tid >> 6;
    const int bx  = blockIdx.x & 7;
    const int by  = blockIdx.x >> 3;
    const int b   = blockIdx.y;
    const int x0  = bx * TILE, y0 = by * TILE;

    const float* fbase = g_feats + (size_t)b * NCH * HW;
    const int oy0 = grp * RPT;
    const int sx  = lx + 12;

    float acc[RPT];
    float bi = __ldg(bias + di);
#pragma unroll
    for (int k = 0; k < RPT; k++) acc[k] = bi;

    auto stage = [&](int c, int sel) {
        const float* plane = fbase + (size_t)c * HW;
        float* dst = sbuf + sel * SBUF;
        for (int idx = tid; idx < NV4; idx += 256) {
            int sy_ = idx / (TW / 4);
            int c4  = idx - sy_ * (TW / 4);
            int gy  = y0 - D + sy_;
            int gx  = x0 - 12 + c4 * 4;
            bool ok = ((unsigned)gy < HH) && ((unsigned)gx < WW);
            const float* src = ok ? (plane + gy * WW + gx) : plane;
            unsigned sa = (unsigned)__cvta_generic_to_shared(dst + sy_ * TW + c4 * 4);
            int sz = ok ? 16 : 0;
            asm volatile("cp.async.cg.shared.global [%0], [%1], 16, %2;\n"
                         :: "r"(sa), "l"(src), "r"(sz));
        }
        asm volatile("cp.async.commit_group;\n" ::: "memory");
    };

    stage(0, 0);
    asm volatile("cp.async.wait_group 0;\n" ::: "memory");
    __syncthreads();

    int cur = 0;
    for (int c = 0; c < nin; c++) {
        if (c + 1 < nin) stage(c + 1, cur ^ 1);

        const float* wp = Wmsd + ((size_t)di * 30 + c) * 9;
        float w0 = __ldg(wp + 0), w1 = __ldg(wp + 1), w2 = __ldg(wp + 2);
        float w3 = __ldg(wp + 3), w4 = __ldg(wp + 4), w5 = __ldg(wp + 5);
        float w6 = __ldg(wp + 6), w7 = __ldg(wp + 7), w8 = __ldg(wp + 8);

        const float* sb_ = sbuf + cur * SBUF;
#pragma unroll
        for (int rr = 0; rr < RPT + 2 * D; rr++) {
            const float* rp = sb_ + (oy0 + rr) * TW + sx;
            float v0 = rp[-D], v1 = rp[0], v2 = rp[D];
            if (rr < RPT)
                acc[rr]       = fmaf(w0, v0, fmaf(w1, v1, fmaf(w2, v2, acc[rr])));
            if (rr >= D && rr < RPT + D)
                acc[rr - D]   = fmaf(w3, v0, fmaf(w4, v1, fmaf(w5, v2, acc[rr - D])));
            if (rr >= 2 * D)
                acc[rr - 2*D] = fmaf(w6, v0, fmaf(w7, v1, fmaf(w8, v2, acc[rr - 2*D])));
        }

        if (c + 1 < nin)
            asm volatile("cp.async.wait_group 0;\n" ::: "memory");
        __syncthreads();
        cur ^= 1;
    }

    float* op = g_feats + (size_t)b * NCH * HW + (size_t)nin * HW
              + (size_t)(y0 + oy0) * WW + (x0 + lx);
#pragma unroll
    for (int k = 0; k < RPT; k++)
        op[(size_t)k * WW] = fmaxf(acc[k], 0.0f);
}

// ---------------------------------------------------------------------------
// EVEN-D depth kernel: identical structure, but thread = column-PAIR x 8 rows
// (32 pairs x 8 groups). Horizontal taps x±D stay pair-aligned for even D ->
// LDS.64 loads, fma.rn.f32x2 math, float2 stores. Instruction count ~halved.
// ---------------------------------------------------------------------------
template<int D>
__global__ void __launch_bounds__(256)
k_depth_pk(const float* __restrict__ Wmsd,
           const float* __restrict__ bias,
           int di) {
    static_assert(D % 2 == 0, "packed kernel requires even D");
    constexpr int TILE = 64;
    constexpr int RPT  = 8;               // output rows per thread
    constexpr int TW   = 88;
    constexpr int TH   = TILE + 2 * D;
    constexpr int SBUF = TH * TW;
    constexpr int NV4  = TH * (TW / 4);

    extern __shared__ float sbuf[];

    const int nin = di + 1;
    const int tid = threadIdx.x;
    const int pr  = tid & 31;             // pair index (columns 2pr, 2pr+1)
    const int grp = tid >> 5;             // 0..7 -> row group
    const int bx  = blockIdx.x & 7;
    const int by  = blockIdx.x >> 3;
    const int b   = blockIdx.y;
    const int x0  = bx * TILE, y0 = by * TILE;

    const float* fbase = g_feats + (size_t)b * NCH * HW;
    const int oy0 = grp * RPT;
    const int sxf = 12 + 2 * pr;          // smem float idx of pair lo lane (even)

    unsigned long long acc[RPT];
    float bi = __ldg(bias + di);
    {
        unsigned long long b2 = pk2(bi);
#pragma unroll
        for (int k = 0; k < RPT; k++) acc[k] = b2;
    }

    auto stage = [&](int c, int sel) {
        const float* plane = fbase + (size_t)c * HW;
        float* dst = sbuf + sel * SBUF;
        for (int idx = tid; idx < NV4; idx += 256) {
            int sy_ = idx / (TW / 4);
            int c4  = idx - sy_ * (TW / 4);
            int gy  = y0 - D + sy_;
            int gx  = x0 - 12 + c4 * 4;
            bool ok = ((unsigned)gy < HH) && ((unsigned)gx < WW);
            const float* src = ok ? (plane + gy * WW + gx) : plane;
            unsigned sa = (unsigned)__cvta_generic_to_shared(dst + sy_ * TW + c4 * 4);
            int sz = ok ? 16 : 0;
            asm volatile("cp.async.cg.shared.global [%0], [%1], 16, %2;\n"
                         :: "r"(sa), "l"(src), "r"(sz));
        }
        asm volatile("cp.async.commit_group;\n" ::: "memory");
    };

    stage(0, 0);
    asm volatile("cp.async.wait_group 0;\n" ::: "memory");
    __syncthreads();

    int cur = 0;
    for (int c = 0; c < nin; c++) {
        if (c + 1 < nin) stage(c + 1, cur ^ 1);

        const float* wp = Wmsd + ((size_t)di * 30 + c) * 9;
        unsigned long long w2[9];
#pragma unroll
        for (int t = 0; t < 9; t++) w2[t] = pk2(__ldg(wp + t));

        const float* sb_ = sbuf + cur * SBUF;
#pragma unroll
        for (int rr = 0; rr < RPT + 2 * D; rr++) {
            const float* rp = sb_ + (oy0 + rr) * TW + sxf;
            unsigned long long v0 = *reinterpret_cast<const unsigned long long*>(rp - D);
            unsigned long long v1 = *reinterpret_cast<const unsigned long long*>(rp);
            unsigned long long v2 = *reinterpret_cast<const unsigned long long*>(rp + D);
            if (rr < RPT) {
                FMA2(acc[rr], v0, w2[0]);
                FMA2(acc[rr], v1, w2[1]);
                FMA2(acc[rr], v2, w2[2]);
            }
            if (rr >= D && rr < RPT + D) {
                FMA2(acc[rr - D], v0, w2[3]);
                FMA2(acc[rr - D], v1, w2[4]);
                FMA2(acc[rr - D], v2, w2[5]);
            }
            if (rr >= 2 * D) {
                FMA2(acc[rr - 2*D], v0, w2[6]);
                FMA2(acc[rr - 2*D], v1, w2[7]);
                FMA2(acc[rr - 2*D], v2, w2[8]);
            }
        }

        if (c + 1 < nin)
            asm volatile("cp.async.wait_group 0;\n" ::: "memory");
        __syncthreads();
        cur ^= 1;
    }

    float* op = g_feats + (size_t)b * NCH * HW + (size_t)nin * HW
              + (size_t)(y0 + oy0) * WW + (x0 + 2 * pr);
#pragma unroll
    for (int k = 0; k < RPT; k++) {
        float lo = __uint_as_float((unsigned)(acc[k] & 0xFFFFFFFFull));
        float hi = __uint_as_float((unsigned)(acc[k] >> 32));
        float2 o = make_float2(fmaxf(lo, 0.0f), fmaxf(hi, 0.0f));
        *reinterpret_cast<float2*>(op + (size_t)k * WW) = o;
    }
}

// ---------------------------------------------------------------------------
// Final 1x1 conv over 31 channels + convB, then sout affine (float4)
// ---------------------------------------------------------------------------
__global__ void k_final(const float* __restrict__ convW,
                        const float* __restrict__ convB,
                        const float* __restrict__ sout_w,
                        const float* __restrict__ sout_b,
                        float* __restrict__ out) {
    int idx = blockIdx.x * blockDim.x + threadIdx.x;   // 0 .. BB*HW/4-1
    int bb = idx >> 16;
    int p  = idx & 65535;
    const float4* f4 = reinterpret_cast<const float4*>(g_feats)
                     + (size_t)(bb * NCH) * (HW / 4) + p;
    float cb = convB[0];
    float4 a = make_float4(cb, cb, cb, cb);
#pragma unroll 4
    for (int c = 0; c < NCH; c++) {
        float wc = __ldg(convW + c);
        float4 v = __ldg(f4 + (size_t)c * (HW / 4));
        a.x = fmaf(wc, v.x, a.x);
        a.y = fmaf(wc, v.y, a.y);
        a.z = fmaf(wc, v.z, a.z);
        a.w = fmaf(wc, v.w, a.w);
    }
    float sw = sout_w[0], sb = sout_b[0];
    float4 r = make_float4(fmaf(a.x, sw, sb), fmaf(a.y, sw, sb),
                           fmaf(a.z, sw, sb), fmaf(a.w, sw, sb));
    reinterpret_cast<float4*>(out)[idx] = r;
}

// ---------------------------------------------------------------------------
// Launch
// ---------------------------------------------------------------------------
template<int D>
static inline void launch_depth_odd(int i, const float* Wmsd, const float* bias) {
    constexpr int TH = 64 + 2 * D;
    int sm = 2 * TH * 88 * (int)sizeof(float);
    cudaFuncSetAttribute(k_depth<D>, cudaFuncAttributeMaxDynamicSharedMemorySize, sm);
    k_depth<D><<<dim3(64, BB), 256, sm>>>(Wmsd, bias, i);
}

template<int D>
static inline void launch_depth_even(int i, const float* Wmsd, const float* bias) {
    constexpr int TH = 64 + 2 * D;
    int sm = 2 * TH * 88 * (int)sizeof(float);
    cudaFuncSetAttribute(k_depth_pk<D>, cudaFuncAttributeMaxDynamicSharedMemorySize, sm);
    k_depth_pk<D><<<dim3(64, BB), 256, sm>>>(Wmsd, bias, i);
}

extern "C" void kernel_launch(void* const* d_in, const int* in_sizes, int n_in,
                              void* d_out, int out_size) {
    const float* x      = (const float*)d_in[0];
    const float* Wmsd   = (const float*)d_in[1];
    const float* bias   = (const float*)d_in[2];
    const float* convW  = (const float*)d_in[3];
    const float* convB  = (const float*)d_in[4];
    const float* sin_w  = (const float*)d_in[5];
    const float* sin_b  = (const float*)d_in[6];
    const float* sout_w = (const float*)d_in[7];
    const float* sout_b = (const float*)d_in[8];
    float* out = (float*)d_out;

    k_init<<<(BB * HW / 4) / 256, 256>>>(x, sin_w, sin_b);

    for (int i = 0; i < 30; i++) {
        int d = (i % 10) + 1;
        switch (d) {
            case  1: launch_depth_odd < 1>(i, Wmsd, bias); break;
            case  2: launch_depth_even< 2>(i, Wmsd, bias); break;
            case  3: launch_depth_odd < 3>(i, Wmsd, bias); break;
            case  4: launch_depth_even< 4>(i, Wmsd, bias); break;
            case  5: launch_depth_odd < 5>(i, Wmsd, bias); break;
            case  6: launch_depth_even< 6>(i, Wmsd, bias); break;
            case  7: launch_depth_odd < 7>(i, Wmsd, bias); break;
            case  8: launch_depth_even< 8>(i, Wmsd, bias); break;
            case  9: launch_depth_odd < 9>(i, Wmsd, bias); break;
            default: launch_depth_even<10>(i, Wmsd, bias); break;
        }
    }

    k_final<<<(BB * HW / 4) / 256, 256>>>(convW, convB, sout_w, sout_b, out);
}

// round 8
// speedup vs baseline: 1.0684x; 1.0684x over previous
#include <cuda_runtime.h>
#include <cstdint>

#define HH 512
#define WW 512
#define BB 4
#define NCH 31          // IN_C + DEPTH
#define HW (HH * WW)

// Scratch: feats tensor [B][31][H][W]  (130 MB device global; written before read)
__device__ float g_feats[(size_t)BB * NCH * HW];

// ---------------------------------------------------------------------------
// Init: feats[:,0] = x * sin_w + sin_b   (float4 vectorized)
// ---------------------------------------------------------------------------
__global__ void k_init(const float* __restrict__ x,
                       const float* __restrict__ sin_w,
                       const float* __restrict__ sin_b) {
    int idx = blockIdx.x * blockDim.x + threadIdx.x;   // 0 .. BB*HW/4-1
    float w = sin_w[0], b = sin_b[0];
    int bb = idx >> 16;            // HW/4 = 65536
    int p  = idx & 65535;
    float4 v = reinterpret_cast<const float4*>(x)[idx];
    float4 r = make_float4(fmaf(v.x, w, b), fmaf(v.y, w, b),
                           fmaf(v.z, w, b), fmaf(v.w, w, b));
    reinterpret_cast<float4*>(g_feats)[(size_t)(bb * NCH) * (HW / 4) + p] = r;
}

// ---------------------------------------------------------------------------
// Single-channel depth kernel (exact R2 champion) — used for D >= 9 where the
// pair kernel's 4 smem buffers would cost CTA residency.
// Tile 64x64, 256 threads, thread = 1 column x 16 rows. Double-buffered
// 88-wide cp.async staging.
// ---------------------------------------------------------------------------
template<int D>
__global__ void __launch_bounds__(256)
k_depth(const float* __restrict__ Wmsd,
        const float* __restrict__ bias,
        int di) {
    constexpr int TILE = 64;
    constexpr int RPT  = 16;
    constexpr int TW   = 88;
    constexpr int TH   = TILE + 2 * D;
    constexpr int SBUF = TH * TW;
    constexpr int NV4  = TH * (TW / 4);

    extern __shared__ float sbuf[];

    const int nin = di + 1;
    const int tid = threadIdx.x;
    const int lx  = tid & 63;
    const int grp = tid >> 6;
    const int bx  = blockIdx.x & 7;
    const int by  = blockIdx.x >> 3;
    const int b   = blockIdx.y;
    const int x0  = bx * TILE, y0 = by * TILE;

    const float* fbase = g_feats + (size_t)b * NCH * HW;
    const int oy0 = grp * RPT;
    const int sx  = lx + 12;

    float acc[RPT];
    float bi = __ldg(bias + di);
#pragma unroll
    for (int k = 0; k < RPT; k++) acc[k] = bi;

    auto stage = [&](int c, int sel) {
        const float* plane = fbase + (size_t)c * HW;
        float* dst = sbuf + sel * SBUF;
        for (int idx = tid; idx < NV4; idx += 256) {
            int sy_ = idx / (TW / 4);
            int c4  = idx - sy_ * (TW / 4);
            int gy  = y0 - D + sy_;
            int gx  = x0 - 12 + c4 * 4;
            bool ok = ((unsigned)gy < HH) && ((unsigned)gx < WW);
            const float* src = ok ? (plane + gy * WW + gx) : plane;
            unsigned sa = (unsigned)__cvta_generic_to_shared(dst + sy_ * TW + c4 * 4);
            int sz = ok ? 16 : 0;
            asm volatile("cp.async.cg.shared.global [%0], [%1], 16, %2;\n"
                         :: "r"(sa), "l"(src), "r"(sz));
        }
        asm volatile("cp.async.commit_group;\n" ::: "memory");
    };

    stage(0, 0);
    asm volatile("cp.async.wait_group 0;\n" ::: "memory");
    __syncthreads();

    int cur = 0;
    for (int c = 0; c < nin; c++) {
        if (c + 1 < nin) stage(c + 1, cur ^ 1);

        const float* wp = Wmsd + ((size_t)di * 30 + c) * 9;
        float w0 = __ldg(wp + 0), w1 = __ldg(wp + 1), w2 = __ldg(wp + 2);
        float w3 = __ldg(wp + 3), w4 = __ldg(wp + 4), w5 = __ldg(wp + 5);
        float w6 = __ldg(wp + 6), w7 = __ldg(wp + 7), w8 = __ldg(wp + 8);

        const float* sb_ = sbuf + cur * SBUF;
#pragma unroll
        for (int rr = 0; rr < RPT + 2 * D; rr++) {
            const float* rp = sb_ + (oy0 + rr) * TW + sx;
            float v0 = rp[-D], v1 = rp[0], v2 = rp[D];
            if (rr < RPT)
                acc[rr]       = fmaf(w0, v0, fmaf(w1, v1, fmaf(w2, v2, acc[rr])));
            if (rr >= D && rr < RPT + D)
                acc[rr - D]   = fmaf(w3, v0, fmaf(w4, v1, fmaf(w5, v2, acc[rr - D])));
            if (rr >= 2 * D)
                acc[rr - 2*D] = fmaf(w6, v0, fmaf(w7, v1, fmaf(w8, v2, acc[rr - 2*D])));
        }

        if (c + 1 < nin)
            asm volatile("cp.async.wait_group 0;\n" ::: "memory");
        __syncthreads();
        cur ^= 1;
    }

    float* op = g_feats + (size_t)b * NCH * HW + (size_t)nin * HW
              + (size_t)(y0 + oy0) * WW + (x0 + lx);
#pragma unroll
    for (int k = 0; k < RPT; k++)
        op[(size_t)k * WW] = fmaxf(acc[k], 0.0f);
}

// ---------------------------------------------------------------------------
// Channel-PAIR depth kernel (D <= 8): identical structure/thread-shape to the
// champion, but each phase processes TWO input channels of the same depth:
// 6 LDS + up to 18 FMA per rr (two independent chains), one barrier+wait per
// pair. Buffer unit = pair (2 channel tiles), double-buffered (4 tiles).
// ---------------------------------------------------------------------------
template<int D>
__global__ void __launch_bounds__(256, 2)
k_depth2(const float* __restrict__ Wmsd,
         const float* __restrict__ bias,
         int di) {
    constexpr int TILE = 64;
    constexpr int RPT  = 16;
    constexpr int TW   = 88;
    constexpr int TH   = TILE + 2 * D;
    constexpr int SBUF = TH * TW;
    constexpr int NV4  = TH * (TW / 4);

    extern __shared__ float sbuf[];       // 4 channel tiles: [sel*2 + ch]

    const int nin    = di + 1;
    const int nphase = (nin + 1) >> 1;
    const int tid = threadIdx.x;
    const int lx  = tid & 63;
    const int grp = tid >> 6;
    const int bx  = blockIdx.x & 7;
    const int by  = blockIdx.x >> 3;
    const int b   = blockIdx.y;
    const int x0  = bx * TILE, y0 = by * TILE;

    const float* fbase = g_feats + (size_t)b * NCH * HW;
    const int oy0 = grp * RPT;
    const int sx  = lx + 12;

    float acc[RPT];
    float bi = __ldg(bias + di);
#pragma unroll
    for (int k = 0; k < RPT; k++) acc[k] = bi;

    // Stage the (1 or 2)-channel pair starting at channel 2*p into pair-buffer
    // sel. One commit group for the whole pair.
    auto stage_pair = [&](int p, int sel) {
        int c0 = 2 * p;
        int nc = (c0 + 1 < nin) ? 2 : 1;
        for (int ch = 0; ch < nc; ch++) {
            const float* plane = fbase + (size_t)(c0 + ch) * HW;
            float* dst = sbuf + (sel * 2 + ch) * SBUF;
            for (int idx = tid; idx < NV4; idx += 256) {
                int sy_ = idx / (TW / 4);
                int c4  = idx - sy_ * (TW / 4);
                int gy  = y0 - D + sy_;
                int gx  = x0 - 12 + c4 * 4;
                bool ok = ((unsigned)gy < HH) && ((unsigned)gx < WW);
                const float* src = ok ? (plane + gy * WW + gx) : plane;
                unsigned sa = (unsigned)__cvta_generic_to_shared(dst + sy_ * TW + c4 * 4);
                int sz = ok ? 16 : 0;
                asm volatile("cp.async.cg.shared.global [%0], [%1], 16, %2;\n"
                             :: "r"(sa), "l"(src), "r"(sz));
            }
        }
        asm volatile("cp.async.commit_group;\n" ::: "memory");
    };

    stage_pair(0, 0);
    asm volatile("cp.async.wait_group 0;\n" ::: "memory");
    __syncthreads();

    int cur = 0;
    for (int ph = 0; ph < nphase; ph++) {
        if (ph + 1 < nphase) stage_pair(ph + 1, cur ^ 1);

        const int c0 = 2 * ph;
        const bool two = (c0 + 1 < nin);
        const float* wpa = Wmsd + ((size_t)di * 30 + c0) * 9;
        float wa0 = __ldg(wpa + 0), wa1 = __ldg(wpa + 1), wa2 = __ldg(wpa + 2);
        float wa3 = __ldg(wpa + 3), wa4 = __ldg(wpa + 4), wa5 = __ldg(wpa + 5);
        float wa6 = __ldg(wpa + 6), wa7 = __ldg(wpa + 7), wa8 = __ldg(wpa + 8);

        const float* sa_ = sbuf + (cur * 2 + 0) * SBUF;
        const float* sb_ = sbuf + (cur * 2 + 1) * SBUF;

        if (two) {
            const float* wpb = wpa + 9;
            float wb0 = __ldg(wpb + 0), wb1 = __ldg(wpb + 1), wb2 = __ldg(wpb + 2);
            float wb3 = __ldg(wpb + 3), wb4 = __ldg(wpb + 4), wb5 = __ldg(wpb + 5);
            float wb6 = __ldg(wpb + 6), wb7 = __ldg(wpb + 7), wb8 = __ldg(wpb + 8);
#pragma unroll
            for (int rr = 0; rr < RPT + 2 * D; rr++) {
                const float* rpa = sa_ + (oy0 + rr) * TW + sx;
                const float* rpb = sb_ + (oy0 + rr) * TW + sx;
                float a0 = rpa[-D], a1 = rpa[0], a2 = rpa[D];
                float b0 = rpb[-D], b1 = rpb[0], b2 = rpb[D];
                if (rr < RPT) {
                    float ta = fmaf(wa0, a0, fmaf(wa1, a1, wa2 * a2));
                    float tb = fmaf(wb0, b0, fmaf(wb1, b1, wb2 * b2));
                    acc[rr] += ta + tb;
                }
                if (rr >= D && rr < RPT + D) {
                    float ta = fmaf(wa3, a0, fmaf(wa4, a1, wa5 * a2));
                    float tb = fmaf(wb3, b0, fmaf(wb4, b1, wb5 * b2));
                    acc[rr - D] += ta + tb;
                }
                if (rr >= 2 * D) {
                    float ta = fmaf(wa6, a0, fmaf(wa7, a1, wa8 * a2));
                    float tb = fmaf(wb6, b0, fmaf(wb7, b1, wb8 * b2));
                    acc[rr - 2*D] += ta + tb;
                }
            }
        } else {
#pragma unroll
            for (int rr = 0; rr < RPT + 2 * D; rr++) {
                const float* rpa = sa_ + (oy0 + rr) * TW + sx;
                float a0 = rpa[-D], a1 = rpa[0], a2 = rpa[D];
                if (rr < RPT)
                    acc[rr]       = fmaf(wa0, a0, fmaf(wa1, a1, fmaf(wa2, a2, acc[rr])));
                if (rr >= D && rr < RPT + D)
                    acc[rr - D]   = fmaf(wa3, a0, fmaf(wa4, a1, fmaf(wa5, a2, acc[rr - D])));
                if (rr >= 2 * D)
                    acc[rr - 2*D] = fmaf(wa6, a0, fmaf(wa7, a1, fmaf(wa8, a2, acc[rr - 2*D])));
            }
        }

        if (ph + 1 < nphase)
            asm volatile("cp.async.wait_group 0;\n" ::: "memory");
        __syncthreads();
        cur ^= 1;
    }

    float* op = g_feats + (size_t)b * NCH * HW + (size_t)nin * HW
              + (size_t)(y0 + oy0) * WW + (x0 + lx);
#pragma unroll
    for (int k = 0; k < RPT; k++)
        op[(size_t)k * WW] = fmaxf(acc[k], 0.0f);
}

// ---------------------------------------------------------------------------
// Final 1x1 conv over 31 channels + convB, then sout affine (float4)
// ---------------------------------------------------------------------------
__global__ void k_final(const float* __restrict__ convW,
                        const float* __restrict__ convB,
                        const float* __restrict__ sout_w,
                        const float* __restrict__ sout_b,
                        float* __restrict__ out) {
    int idx = blockIdx.x * blockDim.x + threadIdx.x;   // 0 .. BB*HW/4-1
    int bb = idx >> 16;
    int p  = idx & 65535;
    const float4* f4 = reinterpret_cast<const float4*>(g_feats)
                     + (size_t)(bb * NCH) * (HW / 4) + p;
    float cb = convB[0];
    float4 a = make_float4(cb, cb, cb, cb);
#pragma unroll 4
    for (int c = 0; c < NCH; c++) {
        float wc = __ldg(convW + c);
        float4 v = __ldg(f4 + (size_t)c * (HW / 4));
        a.x = fmaf(wc, v.x, a.x);
        a.y = fmaf(wc, v.y, a.y);
        a.z = fmaf(wc, v.z, a.z);
        a.w = fmaf(wc, v.w, a.w);
    }
    float sw = sout_w[0], sb = sout_b[0];
    float4 r = make_float4(fmaf(a.x, sw, sb), fmaf(a.y, sw, sb),
                           fmaf(a.z, sw, sb), fmaf(a.w, sw, sb));
    reinterpret_cast<float4*>(out)[idx] = r;
}

// ---------------------------------------------------------------------------
// Launch
// ---------------------------------------------------------------------------
template<int D>
static inline void launch_depth1(int i, const float* Wmsd, const float* bias) {
    constexpr int TH = 64 + 2 * D;
    int sm = 2 * TH * 88 * (int)sizeof(float);
    cudaFuncSetAttribute(k_depth<D>, cudaFuncAttributeMaxDynamicSharedMemorySize, sm);
    k_depth<D><<<dim3(64, BB), 256, sm>>>(Wmsd, bias, i);
}

template<int D>
static inline void launch_depth2(int i, const float* Wmsd, const float* bias) {
    constexpr int TH = 64 + 2 * D;
    int sm = 4 * TH * 88 * (int)sizeof(float);
    cudaFuncSetAttribute(k_depth2<D>, cudaFuncAttributeMaxDynamicSharedMemorySize, sm);
    k_depth2<D><<<dim3(64, BB), 256, sm>>>(Wmsd, bias, i);
}

extern "C" void kernel_launch(void* const* d_in, const int* in_sizes, int n_in,
                              void* d_out, int out_size) {
    const float* x      = (const float*)d_in[0];
    const float* Wmsd   = (const float*)d_in[1];
    const float* bias   = (const float*)d_in[2];
    const float* convW  = (const float*)d_in[3];
    const float* convB  = (const float*)d_in[4];
    const float* sin_w  = (const float*)d_in[5];
    const float* sin_b  = (const float*)d_in[6];
    const float* sout_w = (const float*)d_in[7];
    const float* sout_b = (const float*)d_in[8];
    float* out = (float*)d_out;

    k_init<<<(BB * HW / 4) / 256, 256>>>(x, sin_w, sin_b);

    for (int i = 0; i < 30; i++) {
        int d = (i % 10) + 1;
        switch (d) {
            case  1: launch_depth2<1>(i, Wmsd, bias); break;
            case  2: launch_depth2<2>(i, Wmsd, bias); break;
            case  3: launch_depth2<3>(i, Wmsd, bias); break;
            case  4: launch_depth2<4>(i, Wmsd, bias); break;
            case  5: launch_depth2<5>(i, Wmsd, bias); break;
            case  6: launch_depth2<6>(i, Wmsd, bias); break;
            case  7: launch_depth2<7>(i, Wmsd, bias); break;
            case  8: launch_depth2<8>(i, Wmsd, bias); break;
            case  9: launch_depth1<9>(i, Wmsd, bias); break;
            default: launch_depth1<10>(i, Wmsd, bias); break;
        }
    }

    k_final<<<(BB * HW / 4) / 256, 256>>>(convW, convB, sout_w, sout_b, out);
}

// round 9
// speedup vs baseline: 1.0757x; 1.0068x over previous
#include <cuda_runtime.h>
#include <cstdint>

#define HH 512
#define WW 512
#define BB 4
#define NCH 31          // IN_C + DEPTH
#define HW (HH * WW)

// Scratch: feats tensor [B][31][H][W]  (130 MB device global; written before read)
__device__ float g_feats[(size_t)BB * NCH * HW];

#define FMA2(a, v, w) asm("fma.rn.f32x2 %0, %1, %2, %0;" \
                          : "+l"(a) : "l"(v), "l"(w))

// ---------------------------------------------------------------------------
// Init: feats[:,0] = x * sin_w + sin_b   (float4 vectorized)
// ---------------------------------------------------------------------------
__global__ void k_init(const float* __restrict__ x,
                       const float* __restrict__ sin_w,
                       const float* __restrict__ sin_b) {
    int idx = blockIdx.x * blockDim.x + threadIdx.x;   // 0 .. BB*HW/4-1
    float w = sin_w[0], b = sin_b[0];
    int bb = idx >> 16;            // HW/4 = 65536
    int p  = idx & 65535;
    float4 v = reinterpret_cast<const float4*>(x)[idx];
    float4 r = make_float4(fmaf(v.x, w, b), fmaf(v.y, w, b),
                           fmaf(v.z, w, b), fmaf(v.w, w, b));
    reinterpret_cast<float4*>(g_feats)[(size_t)(bb * NCH) * (HW / 4) + p] = r;
}

// ---------------------------------------------------------------------------
// Depth kernel, templated on dilation D. Structure identical to the R2
// champion: tile 64x64, 256 threads, thread = 1 column x 16 rows, 88-wide
// double-buffered cp.async staging, one wait+barrier per channel.
// ONLY the arithmetic changed: 16 row-accumulators are packed into 8 f32x2
// pairs updated with fma.rn.f32x2 (2 MACs/instr):
//   even D: pairs (2m, 2m+1)  — all vertical taps stay pair-start-aligned
//   odd  D: pairs (m,  m+8)   — stride-8 pairing closed under +D, +2D shifts
// ---------------------------------------------------------------------------
template<int D>
__global__ void __launch_bounds__(256, 3)
k_depth(const float* __restrict__ Wmsd,
        const float* __restrict__ bias,
        int di) {
    constexpr int TILE = 64;
    constexpr int RPT  = 16;
    constexpr int TW   = 88;
    constexpr int TH   = TILE + 2 * D;
    constexpr int SBUF = TH * TW;
    constexpr int NV4  = TH * (TW / 4);

    extern __shared__ float sbuf[];

    const int nin = di + 1;
    const int tid = threadIdx.x;
    const int lx  = tid & 63;
    const int grp = tid >> 6;
    const int bx  = blockIdx.x & 7;
    const int by  = blockIdx.x >> 3;
    const int b   = blockIdx.y;
    const int x0  = bx * TILE, y0 = by * TILE;

    const float* fbase = g_feats + (size_t)b * NCH * HW;
    const int oy0 = grp * RPT;
    const int sx  = lx + 12;

    union F2 { unsigned long long u; float f[2]; };

    F2 P[8];
    {
        float bi = __ldg(bias + di);
#pragma unroll
        for (int m = 0; m < 8; m++) { P[m].f[0] = bi; P[m].f[1] = bi; }
    }

    auto stage = [&](int c, int sel) {
        const float* plane = fbase + (size_t)c * HW;
        float* dst = sbuf + sel * SBUF;
        for (int idx = tid; idx < NV4; idx += 256) {
            int sy_ = idx / (TW / 4);
            int c4  = idx - sy_ * (TW / 4);
            int gy  = y0 - D + sy_;
            int gx  = x0 - 12 + c4 * 4;
            // 16B chunks are 4-float aligned and W is a multiple of 4, so a
            // chunk is either fully inside the row or fully outside -> zfill.
            bool ok = ((unsigned)gy < HH) && ((unsigned)gx < WW);
            const float* src = ok ? (plane + gy * WW + gx) : plane;
            unsigned sa = (unsigned)__cvta_generic_to_shared(dst + sy_ * TW + c4 * 4);
            int sz = ok ? 16 : 0;
            asm volatile("cp.async.cg.shared.global [%0], [%1], 16, %2;\n"
                         :: "r"(sa), "l"(src), "r"(sz));
        }
        asm volatile("cp.async.commit_group;\n" ::: "memory");
    };

    stage(0, 0);
    asm volatile("cp.async.wait_group 0;\n" ::: "memory");
    __syncthreads();

    int cur = 0;
    for (int c = 0; c < nin; c++) {
        if (c + 1 < nin) stage(c + 1, cur ^ 1);

        const float* wp = Wmsd + ((size_t)di * 30 + c) * 9;
        F2 w[9];
#pragma unroll
        for (int t = 0; t < 9; t++) {
            float wv = __ldg(wp + t);
            w[t].f[0] = wv; w[t].f[1] = wv;
        }

        const float* sb_ = sbuf + cur * SBUF;

        if constexpr (D % 2 == 0) {
            // pair rows (2t, 2t+1); pair t feeds P[t] (w-row0),
            // P[t-D/2] (w-row1), P[t-D] (w-row2)
            constexpr int NT = 8 + D;
#pragma unroll
            for (int t = 0; t < NT; t++) {
                const float* rp = sb_ + (oy0 + 2 * t) * TW + sx;
                F2 v0, v1, v2;
                v0.f[0] = rp[-D];     v0.f[1] = rp[TW - D];
                v1.f[0] = rp[0];      v1.f[1] = rp[TW];
                v2.f[0] = rp[D];      v2.f[1] = rp[TW + D];
                if (t < 8) {
                    FMA2(P[t].u, v0.u, w[0].u);
                    FMA2(P[t].u, v1.u, w[1].u);
                    FMA2(P[t].u, v2.u, w[2].u);
                }
                if (t >= D / 2 && t < 8 + D / 2) {
                    FMA2(P[t - D/2].u, v0.u, w[3].u);
                    FMA2(P[t - D/2].u, v1.u, w[4].u);
                    FMA2(P[t - D/2].u, v2.u, w[5].u);
                }
                if (t >= D) {
                    FMA2(P[t - D].u, v0.u, w[6].u);
                    FMA2(P[t - D].u, v1.u, w[7].u);
                    FMA2(P[t - D].u, v2.u, w[8].u);
                }
            }
        } else {
            // pair rows (j, j+8); pair j feeds P[j] (w-row0),
            // P[j-D] (w-row1), P[j-2D] (w-row2)
            constexpr int NJ = 8 + 2 * D;
#pragma unroll
            for (int j = 0; j < NJ; j++) {
                const float* rp = sb_ + (oy0 + j) * TW + sx;
                F2 v0, v1, v2;
                v0.f[0] = rp[-D];     v0.f[1] = rp[8 * TW - D];
                v1.f[0] = rp[0];      v1.f[1] = rp[8 * TW];
                v2.f[0] = rp[D];      v2.f[1] = rp[8 * TW + D];
                if (j < 8) {
                    FMA2(P[j].u, v0.u, w[0].u);
                    FMA2(P[j].u, v1.u, w[1].u);
                    FMA2(P[j].u, v2.u, w[2].u);
                }
                if (j >= D && j < 8 + D) {
                    FMA2(P[j - D].u, v0.u, w[3].u);
                    FMA2(P[j - D].u, v1.u, w[4].u);
                    FMA2(P[j - D].u, v2.u, w[5].u);
                }
                if (j >= 2 * D) {
                    FMA2(P[j - 2*D].u, v0.u, w[6].u);
                    FMA2(P[j - 2*D].u, v1.u, w[7].u);
                    FMA2(P[j - 2*D].u, v2.u, w[8].u);
                }
            }
        }

        if (c + 1 < nin)
            asm volatile("cp.async.wait_group 0;\n" ::: "memory");
        __syncthreads();
        cur ^= 1;
    }

    // ReLU + store new channel (index nin)
    float* opb = g_feats + (size_t)b * NCH * HW + (size_t)nin * HW
               + (size_t)y0 * WW + (x0 + lx);
    if constexpr (D % 2 == 0) {
#pragma unroll
        for (int m = 0; m < 8; m++) {
            opb[(size_t)(oy0 + 2*m    ) * WW] = fmaxf(P[m].f[0], 0.0f);
            opb[(size_t)(oy0 + 2*m + 1) * WW] = fmaxf(P[m].f[1], 0.0f);
        }
    } else {
#pragma unroll
        for (int m = 0; m < 8; m++) {
            opb[(size_t)(oy0 + m    ) * WW] = fmaxf(P[m].f[0], 0.0f);
            opb[(size_t)(oy0 + m + 8) * WW] = fmaxf(P[m].f[1], 0.0f);
        }
    }
}

// ---------------------------------------------------------------------------
// Final 1x1 conv over 31 channels + convB, then sout affine (float4)
// ---------------------------------------------------------------------------
__global__ void k_final(const float* __restrict__ convW,
                        const float* __restrict__ convB,
                        const float* __restrict__ sout_w,
                        const float* __restrict__ sout_b,
                        float* __restrict__ out) {
    int idx = blockIdx.x * blockDim.x + threadIdx.x;   // 0 .. BB*HW/4-1
    int bb = idx >> 16;
    int p  = idx & 65535;
    const float4* f4 = reinterpret_cast<const float4*>(g_feats)
                     + (size_t)(bb * NCH) * (HW / 4) + p;
    float cb = convB[0];
    float4 a = make_float4(cb, cb, cb, cb);
#pragma unroll 4
    for (int c = 0; c < NCH; c++) {
        float wc = __ldg(convW + c);
        float4 v = __ldg(f4 + (size_t)c * (HW / 4));
        a.x = fmaf(wc, v.x, a.x);
        a.y = fmaf(wc, v.y, a.y);
        a.z = fmaf(wc, v.z, a.z);
        a.w = fmaf(wc, v.w, a.w);
    }
    float sw = sout_w[0], sb = sout_b[0];
    float4 r = make_float4(fmaf(a.x, sw, sb), fmaf(a.y, sw, sb),
                           fmaf(a.z, sw, sb), fmaf(a.w, sw, sb));
    reinterpret_cast<float4*>(out)[idx] = r;
}

// ---------------------------------------------------------------------------
// Launch
// ---------------------------------------------------------------------------
template<int D>
static inline void launch_depth(int i, const float* Wmsd, const float* bias) {
    constexpr int TH = 64 + 2 * D;
    int sm = 2 * TH * 88 * (int)sizeof(float);
    cudaFuncSetAttribute(k_depth<D>, cudaFuncAttributeMaxDynamicSharedMemorySize, sm);
    k_depth<D><<<dim3(64, BB), 256, sm>>>(Wmsd, bias, i);
}

extern "C" void kernel_launch(void* const* d_in, const int* in_sizes, int n_in,
                              void* d_out, int out_size) {
    const float* x      = (const float*)d_in[0];
    const float* Wmsd   = (const float*)d_in[1];
    const float* bias   = (const float*)d_in[2];
    const float* convW  = (const float*)d_in[3];
    const float* convB  = (const float*)d_in[4];
    const float* sin_w  = (const float*)d_in[5];
    const float* sin_b  = (const float*)d_in[6];
    const float* sout_w = (const float*)d_in[7];
    const float* sout_b = (const float*)d_in[8];
    float* out = (float*)d_out;

    k_init<<<(BB * HW / 4) / 256, 256>>>(x, sin_w, sin_b);

    for (int i = 0; i < 30; i++) {
        int d = (i % 10) + 1;
        switch (d) {
            case  1: launch_depth< 1>(i, Wmsd, bias); break;
            case  2: launch_depth< 2>(i, Wmsd, bias); break;
            case  3: launch_depth< 3>(i, Wmsd, bias); break;
            case  4: launch_depth< 4>(i, Wmsd, bias); break;
            case  5: launch_depth< 5>(i, Wmsd, bias); break;
            case  6: launch_depth< 6>(i, Wmsd, bias); break;
            case  7: launch_depth< 7>(i, Wmsd, bias); break;
            case  8: launch_depth< 8>(i, Wmsd, bias); break;
            case  9: launch_depth< 9>(i, Wmsd, bias); break;
            default: launch_depth<10>(i, Wmsd, bias); break;
        }
    }

    k_final<<<(BB * HW / 4) / 256, 256>>>(convW, convB, sout_w, sout_b, out);
}